// round 10
// baseline (speedup 1.0000x reference)
#include <cuda_runtime.h>
#include <cuda_fp16.h>
#include <cstdint>

#define SP_O 287496   // 66^3
#define SP_I 262144   // 64^3
#define PLW 68        // padded plane row stride (66 + 2 halo)
#define PL  4488      // 66*68

__device__ float g_sum[32], g_ssum[32];
__device__ uint32_t g_wfrag[1728];   // [tap(27)][nh(2)][lane(32)] packed half2 B-fragments
// fp16 intermediate y, padded layout: [n][co][od(66)][flat plane PL=4488]
__device__ __align__(16) __half g_y[8 * 16 * 66 * PL];

// ---------- helpers ----------
__device__ __forceinline__ uint32_t smem_u32(const void* p) {
    uint32_t a;
    asm("{ .reg .u64 t; cvta.to.shared.u64 t, %1; cvt.u32.u64 %0, t; }" : "=r"(a) : "l"(p));
    return a;
}
__device__ __forceinline__ void ldsm4(uint32_t& a0, uint32_t& a1, uint32_t& a2, uint32_t& a3, uint32_t addr) {
    asm volatile("ldmatrix.sync.aligned.m8n8.x4.shared.b16 {%0,%1,%2,%3}, [%4];"
                 : "=r"(a0), "=r"(a1), "=r"(a2), "=r"(a3) : "r"(addr));
}
__device__ __forceinline__ void mma16816(float* c, uint32_t a0, uint32_t a1, uint32_t a2, uint32_t a3, uint32_t b) {
    asm volatile("mma.sync.aligned.m16n8k16.row.col.f32.f16.f16.f32 "
                 "{%0,%1,%2,%3},{%4,%5,%6,%7},{%8,%9},{%0,%1,%2,%3};"
                 : "+f"(c[0]), "+f"(c[1]), "+f"(c[2]), "+f"(c[3])
                 : "r"(a0), "r"(a1), "r"(a2), "r"(a3), "r"(b), "r"(b));
}
__device__ __forceinline__ uint32_t packh2(float a, float b) {
    __half2 h = __floats2half2_rn(a, b);
    return *reinterpret_cast<uint32_t*>(&h);
}

// ---------- prep: B fragments (fp16-rounded weights) + zero stats ----------
__global__ void prep_weights(const float* __restrict__ w) {
    int idx = blockIdx.x * 256 + threadIdx.x;
    if (idx < 32) { g_sum[idx] = 0.f; g_ssum[idx] = 0.f; }
    if (idx < 1728) {
        int tap = idx >> 6, r = idx & 63, nh = r >> 5, lane = r & 31;
        int ci0 = (lane & 3) * 2, co = nh * 8 + (lane >> 2);
        unsigned short h0 = __half_as_ushort(__float2half(w[(ci0 * 16 + co) * 27 + tap]));
        unsigned short h1 = __half_as_ushort(__float2half(w[((ci0 + 1) * 16 + co) * 27 + tap]));
        g_wfrag[idx] = (uint32_t)h0 | ((uint32_t)h1 << 16);
    }
}

// ---------- stage one input d-slice window: per position 8 hi-halves + 8 lo-halves ----------
__device__ __forceinline__ void stage_slice(const float* __restrict__ x, int n, int d, int f0,
                                            uint4* __restrict__ dst, int tid) {
    for (int i = tid; i < 266; i += 256) {
        int q = f0 - 138 + i;
        float v[8];
        #pragma unroll
        for (int ci = 0; ci < 8; ++ci) v[ci] = 0.f;
        if (q >= 0) {
            int qh = q / PLW, qw = q - qh * PLW;
            if (qh < 64 && qw < 64) {
                const float* xp = x + (size_t)n * 8 * SP_I + (size_t)d * 4096 + qh * 64 + qw;
                #pragma unroll
                for (int ci = 0; ci < 8; ++ci) v[ci] = xp[(size_t)ci * SP_I];
            }
        }
        uint32_t hi[4], lo[4];
        #pragma unroll
        for (int j = 0; j < 4; ++j) {
            float a = v[2 * j], b = v[2 * j + 1];
            hi[j] = packh2(a, b);
            float ha = __half2float(__float2half_rn(a));
            float hb = __half2float(__float2half_rn(b));
            lo[j] = packh2(a - ha, b - hb);
        }
        dst[2 * i]     = make_uint4(hi[0], hi[1], hi[2], hi[3]);
        dst[2 * i + 1] = make_uint4(lo[0], lo[1], lo[2], lo[3]);
    }
}

// ---------- conv: HMMA implicit GEMM; fp16 epilogue via smem transpose ----------
__global__ __launch_bounds__(256, 2) void conv_kernel(const float* __restrict__ x)
{
    __shared__ uint32_t sWf[1728];
    __shared__ __align__(16) uint4 sX[2][532];    // [buf][pos*2] : 16 hi + 16 lo bytes
    __shared__ __align__(16) __half sT[16 * 136]; // [co][pos], row stride 136 halves
    __shared__ float wred[64];

    const int tid = threadIdx.x, warp = tid >> 5, lid = tid & 31;
    const int n = blockIdx.y, f0 = blockIdx.x * 128;

    for (int i = tid; i < 1728; i += 256) sWf[i] = g_wfrag[i];
    stage_slice(x, n, 0, f0, sX[0], tid);

    const uint32_t laneoff = (uint32_t)(((lid & 7) + ((lid >> 3) & 1) * 8) * 32 + ((lid >> 4) & 1) * 16);
    const uint32_t bufb[2] = { smem_u32(sX[0]), smem_u32(sX[1]) };

    const int posAl = warp * 16 + (lid >> 2);      // local 0..127
    const int posBl = posAl + 8;
    const int posA = f0 + posAl, posB = f0 + posBl;
    const bool mA = (posA < PL) && (posA % PLW < 66);
    const bool mB = (posB < PL) && (posB % PLW < 66);
    const int coL = (lid & 3) * 2;
    const int gl  = coL >> 2;

    // chunk-store geometry (uint4 = 8 halves)
    const int sco = tid >> 4, sseg = tid & 15;
    const bool chunkOk = (f0 + sseg * 8) < PL;
    __half* const ybase = g_y + ((size_t)(n * 16 + sco) * 66) * PL + f0 + sseg * 8;
    const __half* const tsrc = sT + sco * 136 + sseg * 8;

    float acc[3][2][4];
    #pragma unroll
    for (int a = 0; a < 3; ++a)
        #pragma unroll
        for (int h = 0; h < 2; ++h)
            #pragma unroll
            for (int r = 0; r < 4; ++r) acc[a][h][r] = 0.f;

    float s4[4] = {0.f, 0.f, 0.f, 0.f};
    float q4[4] = {0.f, 0.f, 0.f, 0.f};
    __syncthreads();

    #pragma unroll 1
    for (int d = 0; d < 64; ++d) {
        if (d < 63) stage_slice(x, n, d + 1, f0, sX[(d + 1) & 1], tid);

        const uint32_t bb = bufb[d & 1];
        #pragma unroll
        for (int s = 0; s < 9; ++s) {
            const int jh = s / 3, jw = s - jh * 3;
            uint32_t a0, a1, a2, a3;
            ldsm4(a0, a1, a2, a3, bb + (uint32_t)((warp * 16 + 138 - jh * PLW - jw) * 32) + laneoff);
            #pragma unroll
            for (int jd = 0; jd < 3; ++jd) {
                const int tap = jd * 9 + s;
                #pragma unroll
                for (int nh = 0; nh < 2; ++nh) {
                    uint32_t b = sWf[tap * 64 + nh * 32 + lid];
                    mma16816(acc[jd][nh], a0, a1, a2, a3, b);
                }
            }
        }

        // od = d complete: ReLU + stats + pack into sT
        #pragma unroll
        for (int nh = 0; nh < 2; ++nh) {
            const int co0 = nh * 8 + coL;
            float v0 = fmaxf(acc[0][nh][0], 0.f), v1 = fmaxf(acc[0][nh][1], 0.f);
            float v2 = fmaxf(acc[0][nh][2], 0.f), v3 = fmaxf(acc[0][nh][3], 0.f);
            sT[co0 * 136 + posAl]       = __float2half_rn(v0);
            sT[(co0 + 1) * 136 + posAl] = __float2half_rn(v1);
            sT[co0 * 136 + posBl]       = __float2half_rn(v2);
            sT[(co0 + 1) * 136 + posBl] = __float2half_rn(v3);
            float sv = 0.f, sq = 0.f;
            if (mA) { sv += v0 + v1; sq += v0 * v0 + v1 * v1; }
            if (mB) { sv += v2 + v3; sq += v2 * v2 + v3 * v3; }
            if (gl) { s4[nh * 2 + 1] += sv; q4[nh * 2 + 1] += sq; }
            else    { s4[nh * 2]     += sv; q4[nh * 2]     += sq; }
        }
        __syncthreads();
        if (chunkOk) *(uint4*)(ybase + (size_t)d * PL) = *(const uint4*)tsrc;

        // rotate accumulators
        #pragma unroll
        for (int nh = 0; nh < 2; ++nh)
            #pragma unroll
            for (int r = 0; r < 4; ++r) {
                acc[0][nh][r] = acc[1][nh][r];
                acc[1][nh][r] = acc[2][nh][r];
                acc[2][nh][r] = 0.f;
            }
        __syncthreads();
    }

    // tails: od = 64 (acc[0]) and od = 65 (acc[1])
    #pragma unroll
    for (int e = 0; e < 2; ++e) {
        #pragma unroll
        for (int nh = 0; nh < 2; ++nh) {
            const int co0 = nh * 8 + coL;
            float v0 = fmaxf(acc[e][nh][0], 0.f), v1 = fmaxf(acc[e][nh][1], 0.f);
            float v2 = fmaxf(acc[e][nh][2], 0.f), v3 = fmaxf(acc[e][nh][3], 0.f);
            sT[co0 * 136 + posAl]       = __float2half_rn(v0);
            sT[(co0 + 1) * 136 + posAl] = __float2half_rn(v1);
            sT[co0 * 136 + posBl]       = __float2half_rn(v2);
            sT[(co0 + 1) * 136 + posBl] = __float2half_rn(v3);
            float sv = 0.f, sq = 0.f;
            if (mA) { sv += v0 + v1; sq += v0 * v0 + v1 * v1; }
            if (mB) { sv += v2 + v3; sq += v2 * v2 + v3 * v3; }
            if (gl) { s4[nh * 2 + 1] += sv; q4[nh * 2 + 1] += sq; }
            else    { s4[nh * 2]     += sv; q4[nh * 2]     += sq; }
        }
        __syncthreads();
        if (chunkOk) *(uint4*)(ybase + (size_t)(64 + e) * PL) = *(const uint4*)tsrc;
        __syncthreads();
    }

    // block reduction of group stats -> atomics
    #pragma unroll
    for (int g = 0; g < 4; ++g) {
        #pragma unroll
        for (int o = 16; o > 0; o >>= 1) {
            s4[g] += __shfl_down_sync(0xffffffffu, s4[g], o);
            q4[g] += __shfl_down_sync(0xffffffffu, q4[g], o);
        }
    }
    if (lid == 0) {
        #pragma unroll
        for (int g = 0; g < 4; ++g) {
            wred[warp * 8 + g]     = s4[g];
            wred[warp * 8 + 4 + g] = q4[g];
        }
    }
    __syncthreads();
    if (tid < 8) {
        float a = 0.f;
        #pragma unroll
        for (int wI = 0; wI < 8; ++wI) a += wred[wI * 8 + tid];
        if (tid < 4) atomicAdd(&g_sum[n * 4 + tid], a);
        else         atomicAdd(&g_ssum[n * 4 + (tid - 4)], a);
    }
}

// ---------- norm: read fp16 padded y, apply GroupNorm affine, write fp32 out ----------
__global__ __launch_bounds__(256) void norm_kernel(float* __restrict__ out,
                                                   const float* __restrict__ gamma,
                                                   const float* __restrict__ beta)
{
    int idx = blockIdx.x * 256 + threadIdx.x;   // float2 index; total 18399744
    int e2 = idx * 2;
    int q  = (unsigned)e2 / 4356u;              // (n*16+c)*66 + od
    int r  = e2 - q * 4356;
    int oh = (unsigned)r / 66u;
    int ow = r - oh * 66;
    int ca = (unsigned)q / 66u;                 // n*16+c
    int c = ca & 15, n = ca >> 4, g = c >> 2;

    const float ic = 1.0f / (4.0f * (float)SP_O);
    int sg = n * 4 + g;
    float m = g_sum[sg] * ic;
    float rs = rsqrtf(g_ssum[sg] * ic - m * m + 1e-5f);
    float a = rs * gamma[c];
    float b = beta[c] - m * a;

    __half2 h = *(const __half2*)(g_y + (size_t)q * PL + oh * PLW + ow);
    float2 v = __half22float2(h);
    float2 o;
    o.x = v.x * a + b;
    o.y = v.y * a + b;
    *(float2*)(out + e2) = o;
}

extern "C" void kernel_launch(void* const* d_in, const int* in_sizes, int n_in,
                              void* d_out, int out_size) {
    const float* x     = (const float*)d_in[0];
    const float* w     = (const float*)d_in[1];
    const float* gamma = (const float*)d_in[2];
    const float* beta  = (const float*)d_in[3];
    float* out = (float*)d_out;

    prep_weights<<<7, 256>>>(w);
    dim3 grid(36, 8);                    // M-tiles (128 flat positions), batch
    conv_kernel<<<grid, 256>>>(x);
    norm_kernel<<<71874, 256>>>(out, gamma, beta);   // 36799488/2/256
}

// round 12
// speedup vs baseline: 1.2145x; 1.2145x over previous
#include <cuda_runtime.h>
#include <cuda_fp16.h>
#include <cstdint>

#define SP_O 287496   // 66^3
#define SP_I 262144   // 64^3
#define PLW 68        // padded plane row stride (66 + 2 halo)
#define PL  4488      // 66*68

__device__ float g_sum[32], g_ssum[32];

__global__ void zero_stats() {
    int t = threadIdx.x;
    g_sum[t] = 0.f;
    g_ssum[t] = 0.f;
}

// ---------- helpers ----------
__device__ __forceinline__ uint32_t smem_u32(const void* p) {
    uint32_t a;
    asm("{ .reg .u64 t; cvta.to.shared.u64 t, %1; cvt.u32.u64 %0, t; }" : "=r"(a) : "l"(p));
    return a;
}
__device__ __forceinline__ void ldsm4(uint32_t& a0, uint32_t& a1, uint32_t& a2, uint32_t& a3, uint32_t addr) {
    asm volatile("ldmatrix.sync.aligned.m8n8.x4.shared.b16 {%0,%1,%2,%3}, [%4];"
                 : "=r"(a0), "=r"(a1), "=r"(a2), "=r"(a3) : "r"(addr));
}
__device__ __forceinline__ void mma16816(float* c, uint32_t a0, uint32_t a1, uint32_t a2, uint32_t a3,
                                         uint32_t b0, uint32_t b1) {
    asm volatile("mma.sync.aligned.m16n8k16.row.col.f32.f16.f16.f32 "
                 "{%0,%1,%2,%3},{%4,%5,%6,%7},{%8,%9},{%0,%1,%2,%3};"
                 : "+f"(c[0]), "+f"(c[1]), "+f"(c[2]), "+f"(c[3])
                 : "r"(a0), "r"(a1), "r"(a2), "r"(a3), "r"(b0), "r"(b1));
}
__device__ __forceinline__ uint32_t packh2(float a, float b) {
    __half2 h = __floats2half2_rn(a, b);
    return *reinterpret_cast<uint32_t*>(&h);
}

// ---------- stage one input d-slice window: per position 8 fp16 ci values (16B) ----------
__device__ __forceinline__ void stage_slice(const float* __restrict__ x, int n, int d, int f0,
                                            uint4* __restrict__ dst, int tid) {
    for (int i = tid; i < 266; i += 256) {
        int q = f0 - 138 + i;
        float v[8];
        #pragma unroll
        for (int ci = 0; ci < 8; ++ci) v[ci] = 0.f;
        if (q >= 0) {
            int qh = q / PLW, qw = q - qh * PLW;
            if (qh < 64 && qw < 64) {
                const float* xp = x + (size_t)n * 8 * SP_I + (size_t)d * 4096 + qh * 64 + qw;
                #pragma unroll
                for (int ci = 0; ci < 8; ++ci) v[ci] = xp[(size_t)ci * SP_I];
            }
        }
        dst[i] = make_uint4(packh2(v[0], v[1]), packh2(v[2], v[3]),
                            packh2(v[4], v[5]), packh2(v[6], v[7]));
    }
}

// ---------- conv: HMMA implicit GEMM with tap-paired K (two taps per MMA) ----------
__global__ __launch_bounds__(256, 2) void conv_kernel(const float* __restrict__ x,
                                                      const float* __restrict__ w,
                                                      float* __restrict__ out)
{
    __shared__ uint32_t sWf[1728];               // [tap(27)][nh(2)][lane(32)]
    __shared__ __align__(16) uint4 sX[2][266];   // [buf][pos] : 8 fp16 ci values
    __shared__ float wred[64];

    const int tid = threadIdx.x, warp = tid >> 5, lid = tid & 31;
    const int n = blockIdx.y, f0 = blockIdx.x * 128;

    // build B fragments in-block (w is L2/L1-resident after first blocks)
    for (int idx = tid; idx < 1728; idx += 256) {
        int tap = idx >> 6, r = idx & 63, nh = r >> 5, lane = r & 31;
        int ci0 = (lane & 3) * 2, co = nh * 8 + (lane >> 2);
        unsigned short h0 = __half_as_ushort(__float2half(__ldg(&w[(ci0 * 16 + co) * 27 + tap])));
        unsigned short h1 = __half_as_ushort(__float2half(__ldg(&w[((ci0 + 1) * 16 + co) * 27 + tap])));
        sWf[idx] = (uint32_t)h0 | ((uint32_t)h1 << 16);
    }
    stage_slice(x, n, 0, f0, sX[0], tid);

    // ldmatrix lane geometry: row r16 of the 16x16 A tile; lanes 16-31 fetch the k8-15
    // half which carries the SECOND tap of the pair (different spatial shift).
    const int r16  = (lid & 7) + ((lid >> 3) & 1) * 8;
    const int half = (lid >> 4) & 1;
    // pair shift table: pair p pairs taps (2p, 2p+1); shifts sh(s) = (s/3)*PLW + s%3
    const int shp0 = half;                 // taps 0,1  -> 0 / 1
    const int shp1 = half ? 68 : 2;        // taps 2,3  -> 2 / 68
    const int shp2 = 69 + half;            // taps 4,5  -> 69 / 70
    const int shp3 = 136 + half;           // taps 6,7  -> 136 / 137
    const int shp4 = 138;                  // tap 8 (single, b1 = 0)
    const uint32_t abase0 = smem_u32(sX[0]) + (uint32_t)((warp * 16 + 138 + r16) * 16);
    const uint32_t abase1 = smem_u32(sX[1]) + (uint32_t)((warp * 16 + 138 + r16) * 16);

    // per-lane store geometry (C frag: c0,c1 -> row posA; c2,c3 -> posA+8; cols 2m,2m+1)
    const int posA = f0 + warp * 16 + (lid >> 2);
    const int posB = posA + 8;
    const int ohA = posA / PLW, owA = posA - ohA * PLW;
    const int ohB = posB / PLW, owB = posB - ohB * PLW;
    const bool mA = (posA < PL) && (owA < 66);
    const bool mB = (posB < PL) && (owB < 66);
    float* const outA = out + (size_t)n * 16 * SP_O + ohA * 66 + owA;
    float* const outB = out + (size_t)n * 16 * SP_O + ohB * 66 + owB;
    const int coL = (lid & 3) * 2;
    const int gl  = coL >> 2;

    float acc[3][2][4];                    // [jd -> od=d+jd][nh][frag]
    #pragma unroll
    for (int a = 0; a < 3; ++a)
        #pragma unroll
        for (int h = 0; h < 2; ++h)
            #pragma unroll
            for (int r = 0; r < 4; ++r) acc[a][h][r] = 0.f;

    float s4[4] = {0.f, 0.f, 0.f, 0.f};
    float q4[4] = {0.f, 0.f, 0.f, 0.f};
    __syncthreads();

    #pragma unroll 1
    for (int d = 0; d < 64; ++d) {
        if (d < 63) stage_slice(x, n, d + 1, f0, sX[(d + 1) & 1], tid);

        const uint32_t ab = (d & 1) ? abase1 : abase0;
        const int shp[5] = {shp0, shp1, shp2, shp3, shp4};
        #pragma unroll
        for (int p = 0; p < 5; ++p) {
            uint32_t a0, a1, a2, a3;
            ldsm4(a0, a1, a2, a3, ab - (uint32_t)(shp[p] * 16));
            const int ta = 2 * p, tb = 2 * p + 1;
            #pragma unroll
            for (int jd = 0; jd < 3; ++jd) {
                #pragma unroll
                for (int nh = 0; nh < 2; ++nh) {
                    uint32_t b0 = sWf[(jd * 9 + ta) * 64 + nh * 32 + lid];
                    uint32_t b1 = (p < 4) ? sWf[(jd * 9 + tb) * 64 + nh * 32 + lid] : 0u;
                    mma16816(acc[jd][nh], a0, a1, a2, a3, b0, b1);
                }
            }
        }

        // od = d complete -> ReLU + store + stats from acc[0]
        {
            const size_t off = (size_t)d * 4356;
            #pragma unroll
            for (int nh = 0; nh < 2; ++nh) {
                const int co0 = nh * 8 + coL;
                float v0 = fmaxf(acc[0][nh][0], 0.f), v1 = fmaxf(acc[0][nh][1], 0.f);
                float v2 = fmaxf(acc[0][nh][2], 0.f), v3 = fmaxf(acc[0][nh][3], 0.f);
                float sv = 0.f, sq = 0.f;
                if (mA) {
                    outA[off + (size_t)co0 * SP_O] = v0;
                    outA[off + (size_t)(co0 + 1) * SP_O] = v1;
                    sv += v0 + v1; sq += v0 * v0 + v1 * v1;
                }
                if (mB) {
                    outB[off + (size_t)co0 * SP_O] = v2;
                    outB[off + (size_t)(co0 + 1) * SP_O] = v3;
                    sv += v2 + v3; sq += v2 * v2 + v3 * v3;
                }
                if (gl) { s4[nh * 2 + 1] += sv; q4[nh * 2 + 1] += sq; }
                else    { s4[nh * 2]     += sv; q4[nh * 2]     += sq; }
            }
        }
        // rotate accumulators: od=d+1 -> slot0, od=d+2 -> slot1, fresh slot2
        #pragma unroll
        for (int nh = 0; nh < 2; ++nh)
            #pragma unroll
            for (int r = 0; r < 4; ++r) {
                acc[0][nh][r] = acc[1][nh][r];
                acc[1][nh][r] = acc[2][nh][r];
                acc[2][nh][r] = 0.f;
            }
        __syncthreads();
    }

    // tails: od = 64 (acc[0]) and od = 65 (acc[1])
    #pragma unroll
    for (int e = 0; e < 2; ++e) {
        const size_t off = (size_t)(64 + e) * 4356;
        #pragma unroll
        for (int nh = 0; nh < 2; ++nh) {
            const int co0 = nh * 8 + coL;
            float v0 = fmaxf(acc[e][nh][0], 0.f), v1 = fmaxf(acc[e][nh][1], 0.f);
            float v2 = fmaxf(acc[e][nh][2], 0.f), v3 = fmaxf(acc[e][nh][3], 0.f);
            float sv = 0.f, sq = 0.f;
            if (mA) {
                outA[off + (size_t)co0 * SP_O] = v0;
                outA[off + (size_t)(co0 + 1) * SP_O] = v1;
                sv += v0 + v1; sq += v0 * v0 + v1 * v1;
            }
            if (mB) {
                outB[off + (size_t)co0 * SP_O] = v2;
                outB[off + (size_t)(co0 + 1) * SP_O] = v3;
                sv += v2 + v3; sq += v2 * v2 + v3 * v3;
            }
            if (gl) { s4[nh * 2 + 1] += sv; q4[nh * 2 + 1] += sq; }
            else    { s4[nh * 2]     += sv; q4[nh * 2]     += sq; }
        }
    }

    // block reduction of group stats -> atomics
    #pragma unroll
    for (int g = 0; g < 4; ++g) {
        #pragma unroll
        for (int o = 16; o > 0; o >>= 1) {
            s4[g] += __shfl_down_sync(0xffffffffu, s4[g], o);
            q4[g] += __shfl_down_sync(0xffffffffu, q4[g], o);
        }
    }
    if (lid == 0) {
        #pragma unroll
        for (int g = 0; g < 4; ++g) {
            wred[warp * 8 + g]     = s4[g];
            wred[warp * 8 + 4 + g] = q4[g];
        }
    }
    __syncthreads();
    if (tid < 8) {
        float a = 0.f;
        #pragma unroll
        for (int wI = 0; wI < 8; ++wI) a += wred[wI * 8 + tid];
        if (tid < 4) atomicAdd(&g_sum[n * 4 + tid], a);
        else         atomicAdd(&g_ssum[n * 4 + (tid - 4)], a);
    }
}

// ---------- norm: in-place GroupNorm affine on fp32 out (finalize folded in) ----------
__global__ __launch_bounds__(256) void norm_kernel(float* __restrict__ out,
                                                   const float* __restrict__ gamma,
                                                   const float* __restrict__ beta)
{
    int idx = blockIdx.x * 256 + threadIdx.x;   // float4 index
    int e = idx * 4;
    int c_all = (unsigned)e / SP_O;             // n*16 + c
    int n = c_all >> 4;
    int c = c_all & 15;
    int g = c >> 2;

    const float ic = 1.0f / (4.0f * (float)SP_O);
    int sg = n * 4 + g;
    float m  = g_sum[sg] * ic;
    float rs = rsqrtf(g_ssum[sg] * ic - m * m + 1e-5f);
    float a = rs * gamma[c];
    float b = beta[c] - m * a;

    float4 v = ((const float4*)out)[idx];
    v.x = v.x * a + b;
    v.y = v.y * a + b;
    v.z = v.z * a + b;
    v.w = v.w * a + b;
    ((float4*)out)[idx] = v;
}

extern "C" void kernel_launch(void* const* d_in, const int* in_sizes, int n_in,
                              void* d_out, int out_size) {
    const float* x     = (const float*)d_in[0];
    const float* w     = (const float*)d_in[1];
    const float* gamma = (const float*)d_in[2];
    const float* beta  = (const float*)d_in[3];
    float* out = (float*)d_out;

    zero_stats<<<1, 32>>>();
    dim3 grid(36, 8);                    // M-tiles (128 flat positions), batch
    conv_kernel<<<grid, 256>>>(x, w, out);
    norm_kernel<<<35937, 256>>>(out, gamma, beta);   // 36799488/4/256
}

// round 16
// speedup vs baseline: 1.2337x; 1.0158x over previous
#include <cuda_runtime.h>
#include <cuda_fp16.h>
#include <cstdint>

#define SP_O 287496   // 66^3
#define SP_I 262144   // 64^3
#define PLW 68        // padded plane row stride (66 + 2 halo)
#define PL  4488      // 66*68

__device__ float g_sum[32], g_ssum[32];          // zero-initialized at module load
__device__ unsigned g_cnt;                        // norm completion counter (zero-init)
__device__ __align__(16) __half g_y[36799488];    // fp16 intermediate y (73.6 MB)

// ---------- helpers ----------
__device__ __forceinline__ uint32_t smem_u32(const void* p) {
    uint32_t a;
    asm("{ .reg .u64 t; cvta.to.shared.u64 t, %1; cvt.u32.u64 %0, t; }" : "=r"(a) : "l"(p));
    return a;
}
__device__ __forceinline__ void ldsm4(uint32_t& a0, uint32_t& a1, uint32_t& a2, uint32_t& a3, uint32_t addr) {
    asm volatile("ldmatrix.sync.aligned.m8n8.x4.shared.b16 {%0,%1,%2,%3}, [%4];"
                 : "=r"(a0), "=r"(a1), "=r"(a2), "=r"(a3) : "r"(addr));
}
__device__ __forceinline__ void mma16816(float* c, uint32_t a0, uint32_t a1, uint32_t a2, uint32_t a3,
                                         uint32_t b0, uint32_t b1) {
    asm volatile("mma.sync.aligned.m16n8k16.row.col.f32.f16.f16.f32 "
                 "{%0,%1,%2,%3},{%4,%5,%6,%7},{%8,%9},{%0,%1,%2,%3};"
                 : "+f"(c[0]), "+f"(c[1]), "+f"(c[2]), "+f"(c[3])
                 : "r"(a0), "r"(a1), "r"(a2), "r"(a3), "r"(b0), "r"(b1));
}
__device__ __forceinline__ uint32_t packh2(float a, float b) {
    __half2 h = __floats2half2_rn(a, b);
    return *reinterpret_cast<uint32_t*>(&h);
}

// ---------- stage one input d-slice window: per position 8 fp16 ci values (16B) ----------
__device__ __forceinline__ void stage_slice(const float* __restrict__ x, int n, int d, int f0,
                                            uint4* __restrict__ dst, int tid) {
    for (int i = tid; i < 266; i += 256) {
        int q = f0 - 138 + i;
        float v[8];
        #pragma unroll
        for (int ci = 0; ci < 8; ++ci) v[ci] = 0.f;
        if (q >= 0) {
            int qh = q / PLW, qw = q - qh * PLW;
            if (qh < 64 && qw < 64) {
                const float* xp = x + (size_t)n * 8 * SP_I + (size_t)d * 4096 + qh * 64 + qw;
                #pragma unroll
                for (int ci = 0; ci < 8; ++ci) v[ci] = xp[(size_t)ci * SP_I];
            }
        }
        dst[i] = make_uint4(packh2(v[0], v[1]), packh2(v[2], v[3]),
                            packh2(v[4], v[5]), packh2(v[6], v[7]));
    }
}

// ---------- conv: HMMA implicit GEMM, tap-paired K; fp16 y epilogue ----------
__global__ __launch_bounds__(256, 2) void conv_kernel(const float* __restrict__ x,
                                                      const float* __restrict__ w)
{
    __shared__ __align__(8) uint2 sWp[960];      // [p(5)][jd(3)][nh(2)][lane(32)] = (b0,b1)
    __shared__ __align__(16) uint4 sX[2][266];   // [buf][pos] : 8 fp16 ci values
    __shared__ float wred[64];

    const int tid = threadIdx.x, warp = tid >> 5, lid = tid & 31;
    const int n = blockIdx.y, f0 = blockIdx.x * 128;

    // build paired B fragments (w L2-resident after first blocks)
    for (int idx = tid; idx < 960; idx += 256) {
        int lane = idx & 31, r = idx >> 5;       // r = (p*3 + jd)*2 + nh
        int nh = r & 1, pj = r >> 1;
        int jd = pj % 3, p = pj / 3;
        int ci0 = (lane & 3) * 2, co = nh * 8 + (lane >> 2);
        int ta = jd * 9 + 2 * p, tb = ta + 1;
        unsigned short a0 = __half_as_ushort(__float2half(__ldg(&w[(ci0 * 16 + co) * 27 + ta])));
        unsigned short a1 = __half_as_ushort(__float2half(__ldg(&w[((ci0 + 1) * 16 + co) * 27 + ta])));
        uint32_t b0 = (uint32_t)a0 | ((uint32_t)a1 << 16);
        uint32_t b1 = 0u;
        if (p < 4) {
            unsigned short c0 = __half_as_ushort(__float2half(__ldg(&w[(ci0 * 16 + co) * 27 + tb])));
            unsigned short c1 = __half_as_ushort(__float2half(__ldg(&w[((ci0 + 1) * 16 + co) * 27 + tb])));
            b1 = (uint32_t)c0 | ((uint32_t)c1 << 16);
        }
        sWp[idx] = make_uint2(b0, b1);
    }
    stage_slice(x, n, 0, f0, sX[0], tid);

    // ldmatrix lane geometry: lanes 16-31 fetch the k8-15 half = SECOND tap of the pair
    const int r16  = (lid & 7) + ((lid >> 3) & 1) * 8;
    const int half = (lid >> 4) & 1;
    const int shp0 = half;                 // taps 0,1
    const int shp1 = half ? 68 : 2;        // taps 2,3
    const int shp2 = 69 + half;            // taps 4,5
    const int shp3 = 136 + half;           // taps 6,7
    const int shp4 = 138;                  // tap 8 (single, b1 = 0)
    const uint32_t abase0 = smem_u32(sX[0]) + (uint32_t)((warp * 16 + 138 + r16) * 16);
    const uint32_t abase1 = smem_u32(sX[1]) + (uint32_t)((warp * 16 + 138 + r16) * 16);

    // per-lane store geometry
    const int posA = f0 + warp * 16 + (lid >> 2);
    const int posB = posA + 8;
    const int ohA = posA / PLW, owA = posA - ohA * PLW;
    const int ohB = posB / PLW, owB = posB - ohB * PLW;
    const bool mA = (posA < PL) && (owA < 66);
    const bool mB = (posB < PL) && (owB < 66);
    __half* const outA = g_y + (size_t)n * 16 * SP_O + ohA * 66 + owA;
    __half* const outB = g_y + (size_t)n * 16 * SP_O + ohB * 66 + owB;
    const int coL = (lid & 3) * 2;
    const int gl  = coL >> 2;

    float acc[3][2][4];                    // [jd -> od=d+jd][nh][frag]
    #pragma unroll
    for (int a = 0; a < 3; ++a)
        #pragma unroll
        for (int h = 0; h < 2; ++h)
            #pragma unroll
            for (int r = 0; r < 4; ++r) acc[a][h][r] = 0.f;

    float s4[4] = {0.f, 0.f, 0.f, 0.f};
    float q4[4] = {0.f, 0.f, 0.f, 0.f};
    __syncthreads();

    #pragma unroll 1
    for (int d = 0; d < 64; ++d) {
        if (d < 63) stage_slice(x, n, d + 1, f0, sX[(d + 1) & 1], tid);

        const uint32_t ab = (d & 1) ? abase1 : abase0;
        const int shp[5] = {shp0, shp1, shp2, shp3, shp4};
        #pragma unroll
        for (int p = 0; p < 5; ++p) {
            uint32_t a0, a1, a2, a3;
            ldsm4(a0, a1, a2, a3, ab - (uint32_t)(shp[p] * 16));
            #pragma unroll
            for (int jd = 0; jd < 3; ++jd) {
                #pragma unroll
                for (int nh = 0; nh < 2; ++nh) {
                    uint2 b = sWp[(((p * 3 + jd) << 1) + nh) * 32 + lid];
                    mma16816(acc[jd][nh], a0, a1, a2, a3, b.x, b.y);
                }
            }
        }

        // od = d complete -> ReLU + fp16 store + stats from acc[0]
        {
            const size_t off = (size_t)d * 4356;
            #pragma unroll
            for (int nh = 0; nh < 2; ++nh) {
                const int co0 = nh * 8 + coL;
                float v0 = fmaxf(acc[0][nh][0], 0.f), v1 = fmaxf(acc[0][nh][1], 0.f);
                float v2 = fmaxf(acc[0][nh][2], 0.f), v3 = fmaxf(acc[0][nh][3], 0.f);
                float sv = 0.f, sq = 0.f;
                if (mA) {
                    outA[off + (size_t)co0 * SP_O]       = __float2half_rn(v0);
                    outA[off + (size_t)(co0 + 1) * SP_O] = __float2half_rn(v1);
                    sv += v0 + v1; sq += v0 * v0 + v1 * v1;
                }
                if (mB) {
                    outB[off + (size_t)co0 * SP_O]       = __float2half_rn(v2);
                    outB[off + (size_t)(co0 + 1) * SP_O] = __float2half_rn(v3);
                    sv += v2 + v3; sq += v2 * v2 + v3 * v3;
                }
                if (gl) { s4[nh * 2 + 1] += sv; q4[nh * 2 + 1] += sq; }
                else    { s4[nh * 2]     += sv; q4[nh * 2]     += sq; }
            }
        }
        // rotate accumulators
        #pragma unroll
        for (int nh = 0; nh < 2; ++nh)
            #pragma unroll
            for (int r = 0; r < 4; ++r) {
                acc[0][nh][r] = acc[1][nh][r];
                acc[1][nh][r] = acc[2][nh][r];
                acc[2][nh][r] = 0.f;
            }
        __syncthreads();
    }

    // tails: od = 64 (acc[0]) and od = 65 (acc[1])
    #pragma unroll
    for (int e = 0; e < 2; ++e) {
        const size_t off = (size_t)(64 + e) * 4356;
        #pragma unroll
        for (int nh = 0; nh < 2; ++nh) {
            const int co0 = nh * 8 + coL;
            float v0 = fmaxf(acc[e][nh][0], 0.f), v1 = fmaxf(acc[e][nh][1], 0.f);
            float v2 = fmaxf(acc[e][nh][2], 0.f), v3 = fmaxf(acc[e][nh][3], 0.f);
            float sv = 0.f, sq = 0.f;
            if (mA) {
                outA[off + (size_t)co0 * SP_O]       = __float2half_rn(v0);
                outA[off + (size_t)(co0 + 1) * SP_O] = __float2half_rn(v1);
                sv += v0 + v1; sq += v0 * v0 + v1 * v1;
            }
            if (mB) {
                outB[off + (size_t)co0 * SP_O]       = __float2half_rn(v2);
                outB[off + (size_t)(co0 + 1) * SP_O] = __float2half_rn(v3);
                sv += v2 + v3; sq += v2 * v2 + v3 * v3;
            }
            if (gl) { s4[nh * 2 + 1] += sv; q4[nh * 2 + 1] += sq; }
            else    { s4[nh * 2]     += sv; q4[nh * 2]     += sq; }
        }
    }

    // block reduction of group stats -> atomics
    #pragma unroll
    for (int g = 0; g < 4; ++g) {
        #pragma unroll
        for (int o = 16; o > 0; o >>= 1) {
            s4[g] += __shfl_down_sync(0xffffffffu, s4[g], o);
            q4[g] += __shfl_down_sync(0xffffffffu, q4[g], o);
        }
    }
    if (lid == 0) {
        #pragma unroll
        for (int g = 0; g < 4; ++g) {
            wred[warp * 8 + g]     = s4[g];
            wred[warp * 8 + 4 + g] = q4[g];
        }
    }
    __syncthreads();
    if (tid < 8) {
        float a = 0.f;
        #pragma unroll
        for (int wI = 0; wI < 8; ++wI) a += wred[wI * 8 + tid];
        if (tid < 4) atomicAdd(&g_sum[n * 4 + tid], a);
        else         atomicAdd(&g_ssum[n * 4 + (tid - 4)], a);
    }
}

// ---------- norm: read fp16 y, GroupNorm affine, write fp32 out; last block re-zeros stats ----------
__global__ __launch_bounds__(256) void norm_kernel(float* __restrict__ out,
                                                   const float* __restrict__ gamma,
                                                   const float* __restrict__ beta)
{
    int idx = blockIdx.x * 256 + threadIdx.x;   // 4-element group
    int e = idx * 4;
    int c_all = (unsigned)e / SP_O;             // n*16 + c
    int n = c_all >> 4;
    int c = c_all & 15;
    int g = c >> 2;

    const float ic = 1.0f / (4.0f * (float)SP_O);
    int sg = n * 4 + g;
    float m  = g_sum[sg] * ic;
    float rs = rsqrtf(g_ssum[sg] * ic - m * m + 1e-5f);
    float a = rs * gamma[c];
    float b = beta[c] - m * a;

    uint2 hh = *(const uint2*)(g_y + e);
    __half2 h0 = *reinterpret_cast<__half2*>(&hh.x);
    __half2 h1 = *reinterpret_cast<__half2*>(&hh.y);
    float2 f0 = __half22float2(h0), f1 = __half22float2(h1);
    float4 v;
    v.x = f0.x * a + b;
    v.y = f0.y * a + b;
    v.z = f1.x * a + b;
    v.w = f1.y * a + b;
    ((float4*)out)[idx] = v;

    // re-zero stats for the next graph replay once every block has read them
    __syncthreads();
    if (threadIdx.x == 0) {
        unsigned vdone = atomicAdd(&g_cnt, 1u);
        if (vdone == gridDim.x - 1) {
            #pragma unroll
            for (int i = 0; i < 32; ++i) { g_sum[i] = 0.f; g_ssum[i] = 0.f; }
            g_cnt = 0u;
        }
    }
}

extern "C" void kernel_launch(void* const* d_in, const int* in_sizes, int n_in,
                              void* d_out, int out_size) {
    const float* x     = (const float*)d_in[0];
    const float* w     = (const float*)d_in[1];
    const float* gamma = (const float*)d_in[2];
    const float* beta  = (const float*)d_in[3];
    float* out = (float*)d_out;

    dim3 grid(36, 8);                    // M-tiles (128 flat positions), batch
    conv_kernel<<<grid, 256>>>(x, w);
    norm_kernel<<<35937, 256>>>(out, gamma, beta);   // 36799488/4/256
}